// round 17
// baseline (speedup 1.0000x reference)
#include <cuda_runtime.h>
#include <cuda_bf16.h>
#include <cstdint>

#define B_      64
#define L_      512
#define D_      768
#define NF_     100
#define WAIST_  768
#define KTOT    868
#define ESTR    104
#define KTILES  56            // K padded to 896 with zeros
#define KSKIP   48            // seq-region k-tiles (768/16)
#define NNT     6

#define NSTG    3
#define STGB    32768         // bytes per stage: 2 k-tiles x (Ahi,Alo,Bhi,Blo) x 4KB
#define STGWRD  8192          // words per stage

// ---------------------------------------------------------------------------
// Global scratch (__device__ globals only)
// ---------------------------------------------------------------------------
__device__ int g_gidx[B_ * L_];
__device__ int g_nvalid[B_];
__device__ uint32_t g_Xhi[(size_t)256 * KTILES * 1024];  // [tile][kt][m][8] (perm j)
__device__ uint32_t g_Xlo[(size_t)256 * KTILES * 1024];
__device__ uint32_t g_Whi[KTILES * WAIST_ * 8];          // [kt][n][8] (perm j)
__device__ uint32_t g_Wlo[KTILES * WAIST_ * 8];
__device__ float    g_tagp[256 * NNT * 384];             // per-(tile,nt) tag partials

// ---------------------------------------------------------------------------
// helpers
// ---------------------------------------------------------------------------
__device__ __forceinline__ int permf(int j) { return (j & 3) * 2 + (j >> 2); }

__device__ __forceinline__ uint32_t pack_split(float f0, float f1, uint32_t& lo_out)
{
    __nv_bfloat16 h0 = __float2bfloat16(f0);
    __nv_bfloat16 h1 = __float2bfloat16(f1);
    __nv_bfloat16 l0 = __float2bfloat16(f0 - __bfloat162float(h0));
    __nv_bfloat16 l1 = __float2bfloat16(f1 - __bfloat162float(h1));
    __nv_bfloat162 hp; hp.x = h0; hp.y = h1;
    __nv_bfloat162 lp; lp.x = l0; lp.y = l1;
    lo_out = *reinterpret_cast<uint32_t*>(&lp);
    return *reinterpret_cast<uint32_t*>(&hp);
}

// pack 16 consecutive-k floats into 8 perm-ordered hi/lo words, store as 2+2 uint4
__device__ __forceinline__ void pack_row16(const float v[16],
                                           uint32_t* __restrict__ oh,
                                           uint32_t* __restrict__ ol)
{
    uint32_t hi[8], lo[8];
    #pragma unroll
    for (int j = 0; j < 8; j++) {
        int p = permf(j);
        hi[p] = pack_split(v[2 * j], v[2 * j + 1], lo[p]);
    }
    *(uint4*)(oh)     = make_uint4(hi[0], hi[1], hi[2], hi[3]);
    *(uint4*)(oh + 4) = make_uint4(hi[4], hi[5], hi[6], hi[7]);
    *(uint4*)(ol)     = make_uint4(lo[0], lo[1], lo[2], lo[3]);
    *(uint4*)(ol + 4) = make_uint4(lo[4], lo[5], lo[6], lo[7]);
}

__device__ __forceinline__ void mma_bf16(float c[4], const uint32_t a[4],
                                         const uint32_t b[2])
{
    asm volatile(
        "mma.sync.aligned.m16n8k16.row.col.f32.bf16.bf16.f32 "
        "{%0,%1,%2,%3},{%4,%5,%6,%7},{%8,%9},{%0,%1,%2,%3};"
        : "+f"(c[0]), "+f"(c[1]), "+f"(c[2]), "+f"(c[3])
        : "r"(a[0]), "r"(a[1]), "r"(a[2]), "r"(a[3]), "r"(b[0]), "r"(b[1]));
}

__device__ __forceinline__ void cpa16(uint32_t dst_smem, const void* src)
{
    asm volatile("cp.async.cg.shared.global [%0], [%1], 16;\n"
                 :: "r"(dst_smem), "l"(src));
}

// ---------------------------------------------------------------------------
// Kernel 1: compaction index + per-batch valid count
// ---------------------------------------------------------------------------
__global__ void compact_kernel(const int* __restrict__ valid)
{
    int b = blockIdx.x;
    int t = threadIdx.x;                 // 512
    int v = valid[b * L_ + t];
    g_gidx[b * L_ + t] = -1;

    __shared__ int warp_tot[16];
    unsigned mask = __ballot_sync(0xffffffffu, v != 0);
    int lane = t & 31, w = t >> 5;
    int intra = __popc(mask & ((1u << lane) - 1u));
    if (lane == 31) warp_tot[w] = __popc(mask);
    __syncthreads();
    int offset = 0;
    for (int i = 0; i < w; i++) offset += warp_tot[i];
    if (v) g_gidx[b * L_ + offset + intra] = t;
    if (t == L_ - 1) g_nvalid[b] = offset + __popc(mask);
}

// ---------------------------------------------------------------------------
// Kernel 2: cls head
// ---------------------------------------------------------------------------
__global__ void cls_kernel(const float* __restrict__ seq,
                           const float* __restrict__ cls_w,
                           const float* __restrict__ cls_b,
                           float* __restrict__ out)
{
    int b = blockIdx.x;
    int t = threadIdx.x;                 // 256
    const float* row = seq + (size_t)b * L_ * D_;
    float p0 = 0.f, p1 = 0.f;
    for (int d = t; d < D_; d += 256) {
        float x = row[d];
        p0 += x * cls_w[d * 2 + 0];
        p1 += x * cls_w[d * 2 + 1];
    }
    __shared__ float s0[256], s1[256];
    s0[t] = p0; s1[t] = p1;
    __syncthreads();
    for (int s = 128; s > 0; s >>= 1) {
        if (t < s) { s0[t] += s0[t + s]; s1[t] += s1[t + s]; }
        __syncthreads();
    }
    if (t == 0) {
        out[b * 2 + 0] = s0[0] + cls_b[0];
        out[b * 2 + 1] = s1[0] + cls_b[1];
    }
}

// ---------------------------------------------------------------------------
// Kernel 3: split w1 -> g_Whi/g_Wlo[kt][n][perm(j)], row-per-thread coalesced
// ---------------------------------------------------------------------------
__global__ void prepw_kernel(const float* __restrict__ w1)
{
    int kt = blockIdx.x;     // 0..55
    int n  = threadIdx.x;    // 0..767
    float v[16];
    #pragma unroll
    for (int kk = 0; kk < 16; kk++) {
        int k = kt * 16 + kk;
        v[kk] = (k < KTOT) ? w1[(size_t)k * WAIST_ + n] : 0.f;
    }
    int base = (kt * WAIST_ + n) * 8;
    pack_row16(v, g_Whi + base, g_Wlo + base);
}

// ---------------------------------------------------------------------------
// Kernel 4: X planes (gather + enrichment + split); row-per-thread stores
// ---------------------------------------------------------------------------
__global__ __launch_bounds__(256, 2)
void prepx_kernel(const float* __restrict__ seq,
                  const float* __restrict__ feat,
                  const float* __restrict__ enr_w,
                  const float* __restrict__ enr_b)
{
    extern __shared__ float sm[];
    float* E  = sm;                   // 128*ESTR
    float* Fs = sm + 128 * ESTR;
    __shared__ int s_src[128];

    int b    = blockIdx.y;
    int mblk = blockIdx.x;
    int m0   = mblk * 128;
    int tid  = threadIdx.x;

    if (tid < 128) s_src[tid] = g_gidx[b * L_ + m0 + tid];

    for (int i = tid; i < 128 * NF_; i += 256) {
        int m = i / NF_, c = i % NF_;
        Fs[m * ESTR + c] = feat[((size_t)(b * L_ + m0 + m)) * NF_ + c];
    }
    __syncthreads();
    for (int gg = tid; gg < 32 * ESTR; gg += 256) {
        int f  = gg % ESTR;
        int mq = gg / ESTR;
        float a0 = 0.f, a1 = 0.f, a2 = 0.f, a3 = 0.f;
        if (f < NF_) {
            float bb = __ldg(&enr_b[f]);
            a0 = bb; a1 = bb; a2 = bb; a3 = bb;
            const float* f0 = Fs + (mq * 4 + 0) * ESTR;
            const float* f1 = Fs + (mq * 4 + 1) * ESTR;
            const float* f2 = Fs + (mq * 4 + 2) * ESTR;
            const float* f3 = Fs + (mq * 4 + 3) * ESTR;
            #pragma unroll 4
            for (int k = 0; k < NF_; k++) {
                float w = __ldg(&enr_w[k * NF_ + f]);
                a0 += f0[k] * w; a1 += f1[k] * w;
                a2 += f2[k] * w; a3 += f3[k] * w;
            }
            a0 = fmaxf(a0, 0.f); a1 = fmaxf(a1, 0.f);
            a2 = fmaxf(a2, 0.f); a3 = fmaxf(a3, 0.f);
        }
        E[(mq * 4 + 0) * ESTR + f] = a0;
        E[(mq * 4 + 1) * ESTR + f] = a1;
        E[(mq * 4 + 2) * ESTR + f] = a2;
        E[(mq * 4 + 3) * ESTR + f] = a3;
    }
    __syncthreads();

    size_t tile = (size_t)(b * 4 + mblk);
    uint32_t* oh = g_Xhi + tile * KTILES * 1024;
    uint32_t* ol = g_Xlo + tile * KTILES * 1024;
    bool skip = (m0 >= g_nvalid[b]);     // whole tile zero in seq region

    if (!skip) {
        // seq region: one thread per (kt, m) row; 64B read, 2x32B stores/plane
        for (int u = tid; u < KSKIP * 128; u += 256) {
            int kt = u >> 7, m = u & 127;    // consecutive tid -> consecutive m
            int s = s_src[m];
            float v[16];
            if (s >= 0) {
                const float4* p = (const float4*)(seq + ((size_t)(b * L_ + s)) * D_ + kt * 16);
                #pragma unroll
                for (int q = 0; q < 4; q++) {
                    float4 x = p[q];
                    v[q * 4 + 0] = x.x; v[q * 4 + 1] = x.y;
                    v[q * 4 + 2] = x.z; v[q * 4 + 3] = x.w;
                }
            } else {
                #pragma unroll
                for (int q = 0; q < 16; q++) v[q] = 0.f;
            }
            int base = kt * 1024 + m * 8;
            pack_row16(v, oh + base, ol + base);
        }
    }
    // enrichment region: kt 48..54
    for (int u = tid; u < 7 * 128; u += 256) {
        int kt = 48 + (u >> 7), m = u & 127;
        int c0 = (kt - 48) * 16;
        float v[16];
        #pragma unroll
        for (int q = 0; q < 4; q++) {
            int col = c0 + q * 4;
            float4 x = make_float4(0.f, 0.f, 0.f, 0.f);
            if (col < ESTR) x = *(const float4*)(E + m * ESTR + col);
            v[q * 4 + 0] = x.x; v[q * 4 + 1] = x.y;
            v[q * 4 + 2] = x.z; v[q * 4 + 3] = x.w;
        }
        int base = kt * 1024 + m * 8;
        pack_row16(v, oh + base, ol + base);
    }
    // kt 55: zero pad (read by gemm in pair (54,55))
    {
        uint4 z = make_uint4(0u, 0u, 0u, 0u);
        *(uint4*)(oh + 55 * 1024 + tid * 4) = z;
        *(uint4*)(ol + 55 * 1024 + tid * 4) = z;
    }
}

// ---------------------------------------------------------------------------
// Kernel 5: GEMM, one CTA per (tile, nt). 2-ktile stages, 3-deep cp.async,
// LDS.64 fragment loads, running-pointer fills.
// ---------------------------------------------------------------------------
__global__ __launch_bounds__(256, 2)
void gemm_kernel(const float* __restrict__ b1,
                 const float* __restrict__ w2)
{
    extern __shared__ uint32_t smw[];            // NSTG x 8192 words
    __shared__ float s_tagp[4][128][3];

    int nt   = blockIdx.x;                       // 0..5
    int tile = blockIdx.y;                       // 0..255
    int b    = tile >> 2, mblk = tile & 3;
    int n0   = nt * 128;
    int tid  = threadIdx.x;
    int warp = tid >> 5, lane = tid & 31;
    int wy = warp >> 2, wx = warp & 3;
    int g  = lane >> 2, t4 = lane & 3;

    int kstart = (mblk * 128 >= g_nvalid[b]) ? KSKIP : 0;
    int npair  = (KTILES - kstart) >> 1;         // 28 or 4

    for (int i = tid; i < 4 * 128 * 3; i += 256)
        (&s_tagp[0][0][0])[i] = 0.f;

    uint32_t smem_base = (uint32_t)__cvta_generic_to_shared(smw);

    // running fill pointers (advance by constant strides)
    const uint32_t* pXH = g_Xhi + (size_t)tile * KTILES * 1024 + kstart * 1024 + tid * 4;
    const uint32_t* pXL = g_Xlo + (size_t)tile * KTILES * 1024 + kstart * 1024 + tid * 4;
    const uint32_t* pWh = g_Whi + ((size_t)kstart * WAIST_ + n0) * 8 + tid * 4;
    const uint32_t* pWl = g_Wlo + ((size_t)kstart * WAIST_ + n0) * 8 + tid * 4;
    uint32_t fb = smem_base + (uint32_t)(tid * 16);
    uint32_t fb_end = smem_base + (uint32_t)(NSTG * STGB);

    #define FILL() do {                                                         \
        cpa16(fb,         pXH);        cpa16(fb + 4096,  pXL);                  \
        cpa16(fb + 8192,  pWh);        cpa16(fb + 12288, pWl);                  \
        cpa16(fb + 16384, pXH + 1024); cpa16(fb + 20480, pXL + 1024);           \
        cpa16(fb + 24576, pWh + 6144); cpa16(fb + 28672, pWl + 6144);           \
        asm volatile("cp.async.commit_group;\n" ::: "memory");                  \
        pXH += 2048; pXL += 2048; pWh += 12288; pWl += 12288;                   \
        fb += STGB; if (fb >= fb_end + (uint32_t)(tid * 16) - (uint32_t)0 && fb >= smem_base + (uint32_t)(NSTG * STGB)) fb -= (uint32_t)(NSTG * STGB); \
    } while (0)

    float acc[4][4][4];
    #pragma unroll
    for (int mt = 0; mt < 4; mt++)
        #pragma unroll
        for (int nn = 0; nn < 4; nn++)
            #pragma unroll
            for (int q = 0; q < 4; q++) acc[mt][nn][q] = 0.f;

    FILL(); FILL();

    for (int i = 0; i < npair; i++) {
        if (i == npair - 1)
            asm volatile("cp.async.wait_group 0;\n" ::: "memory");
        else
            asm volatile("cp.async.wait_group 1;\n" ::: "memory");
        __syncthreads();                 // stage i ready; stage i-1 reads done
        if (i + 2 < npair) FILL();

        uint32_t* stage = smw + (i % NSTG) * STGWRD;
        #pragma unroll
        for (int sub = 0; sub < 2; sub++) {
            const uint2* Ah64 = (const uint2*)(stage + sub * 4096);
            const uint2* Al64 = (const uint2*)(stage + sub * 4096 + 1024);
            const uint2* Bh64 = (const uint2*)(stage + sub * 4096 + 2048);
            const uint2* Bl64 = (const uint2*)(stage + sub * 4096 + 3072);

            uint32_t Bh[4][2], Bl[4][2];
            #pragma unroll
            for (int nn = 0; nn < 4; nn++) {
                int nb = wx * 32 + nn * 8 + g;
                uint2 h = Bh64[nb * 4 + t4];
                uint2 l = Bl64[nb * 4 + t4];
                Bh[nn][0] = h.x; Bh[nn][1] = h.y;
                Bl[nn][0] = l.x; Bl[nn][1] = l.y;
            }
            #pragma unroll
            for (int mt = 0; mt < 4; mt++) {
                int rm = wy * 64 + mt * 16 + g;
                uint2 ah0 = Ah64[rm * 4 + t4];
                uint2 ah1 = Ah64[(rm + 8) * 4 + t4];
                uint2 al0 = Al64[rm * 4 + t4];
                uint2 al1 = Al64[(rm + 8) * 4 + t4];
                uint32_t Ah[4] = {ah0.x, ah1.x, ah0.y, ah1.y};
                uint32_t Al[4] = {al0.x, al1.x, al0.y, al1.y};
                #pragma unroll
                for (int nn = 0; nn < 4; nn++) {
                    mma_bf16(acc[mt][nn], Ah, Bl[nn]);   // small terms first
                    mma_bf16(acc[mt][nn], Al, Bh[nn]);
                    mma_bf16(acc[mt][nn], Ah, Bh[nn]);
                }
            }
        }
    }

    // epilogue: bias + relu + tag partials for this nt
    #pragma unroll
    for (int mt = 0; mt < 4; mt++) {
        float tg0[3] = {0.f, 0.f, 0.f};
        float tg1[3] = {0.f, 0.f, 0.f};
        #pragma unroll
        for (int nn = 0; nn < 4; nn++) {
            #pragma unroll
            for (int cc = 0; cc < 2; cc++) {
                int n = n0 + wx * 32 + nn * 8 + 2 * t4 + cc;
                float bias = __ldg(&b1[n]);
                float w20 = __ldg(&w2[n * 3 + 0]);
                float w21 = __ldg(&w2[n * 3 + 1]);
                float w22 = __ldg(&w2[n * 3 + 2]);
                float h0 = fmaxf(acc[mt][nn][cc]     + bias, 0.f);
                float h1 = fmaxf(acc[mt][nn][cc + 2] + bias, 0.f);
                tg0[0] += h0 * w20; tg0[1] += h0 * w21; tg0[2] += h0 * w22;
                tg1[0] += h1 * w20; tg1[1] += h1 * w21; tg1[2] += h1 * w22;
            }
        }
        #pragma unroll
        for (int t3 = 0; t3 < 3; t3++) {
            tg0[t3] += __shfl_xor_sync(0xffffffffu, tg0[t3], 1);
            tg0[t3] += __shfl_xor_sync(0xffffffffu, tg0[t3], 2);
            tg1[t3] += __shfl_xor_sync(0xffffffffu, tg1[t3], 1);
            tg1[t3] += __shfl_xor_sync(0xffffffffu, tg1[t3], 2);
        }
        if (t4 == 0) {
            int r0 = wy * 64 + mt * 16 + g;
            #pragma unroll
            for (int t3 = 0; t3 < 3; t3++) {
                s_tagp[wx][r0][t3]     = tg0[t3];
                s_tagp[wx][r0 + 8][t3] = tg1[t3];
            }
        }
    }
    __syncthreads();
    // fixed-order wx sum -> global partials for (tile, nt)
    float* dst = g_tagp + (size_t)(tile * NNT + nt) * 384;
    for (int i = tid; i < 384; i += 256) {
        int m = i / 3, t = i % 3;
        dst[i] = s_tagp[0][m][t] + s_tagp[1][m][t]
               + s_tagp[2][m][t] + s_tagp[3][m][t];
    }
    #undef FILL
}

// ---------------------------------------------------------------------------
// Kernel 6: sum nt partials (fixed order) + b2 -> tag_logits
// ---------------------------------------------------------------------------
__global__ void tagred_kernel(const float* __restrict__ b2,
                              float* __restrict__ out)
{
    int tile = blockIdx.x;
    int i = threadIdx.x;                 // 384
    int b = tile >> 2, mblk = tile & 3;
    int m = i / 3, t = i % 3;
    float v = __ldg(&b2[t]);
    #pragma unroll
    for (int nt = 0; nt < NNT; nt++)
        v += g_tagp[(size_t)(tile * NNT + nt) * 384 + i];
    out[128 + ((size_t)(b * L_ + mblk * 128 + m)) * 3 + t] = v;
}

// ---------------------------------------------------------------------------
extern "C" void kernel_launch(void* const* d_in, const int* in_sizes, int n_in,
                              void* d_out, int out_size)
{
    const float* seq   = (const float*)d_in[0];
    const float* feat  = (const float*)d_in[1];
    const int*   valid = (const int*)  d_in[2];
    const float* enr_w = (const float*)d_in[3];
    const float* enr_b = (const float*)d_in[4];
    const float* w1    = (const float*)d_in[5];
    const float* b1    = (const float*)d_in[6];
    const float* w2    = (const float*)d_in[7];
    const float* b2    = (const float*)d_in[8];
    const float* cls_w = (const float*)d_in[9];
    const float* cls_b = (const float*)d_in[10];
    float* out = (float*)d_out;

    const int smem_prep = 2 * 128 * ESTR * (int)sizeof(float);   // 106,496 B
    const int smem_gemm = NSTG * STGB;                           // 98,304 B
    cudaFuncSetAttribute(prepx_kernel, cudaFuncAttributeMaxDynamicSharedMemorySize, smem_prep);
    cudaFuncSetAttribute(gemm_kernel,  cudaFuncAttributeMaxDynamicSharedMemorySize, smem_gemm);

    compact_kernel<<<B_, L_>>>(valid);
    prepw_kernel<<<KTILES, WAIST_>>>(w1);
    prepx_kernel<<<dim3(4, B_), 256, smem_prep>>>(seq, feat, enr_w, enr_b);
    gemm_kernel<<<dim3(NNT, 256), 256, smem_gemm>>>(b1, w2);
    tagred_kernel<<<256, 384>>>(b2, out);
    cls_kernel<<<B_, 256>>>(seq, cls_w, cls_b, out);
}